// round 9
// baseline (speedup 1.0000x reference)
#include <cuda_runtime.h>
#include <cuda_bf16.h>
#include <math.h>

typedef unsigned int u32;

#define T_DIM 1024
#define B_DIM 64
#define D_DIM 512
#define N_DIM 64
#define BN_ (B_DIM * N_DIM)          /* 4096 */
#define TBN_ (T_DIM * BN_)           /* 4,194,304 */

// Packed gate scratch, padded by EIGHT timesteps for the depth-7 ring.
// g_kq : per (t,b,j): {k, q}   -> lane loads float4 = (k0,q0,k1,q1)
// g_ewv: per (t,b,i): {e, wv}  -> warp broadcast float2
__device__ float g_kq [(TBN_ + 8 * BN_) * 2];
__device__ float g_ewv[(TBN_ + 8 * BN_) * 2];

// Concatenated weights, bf16 hi/lo split. Row order:
// [0:64)=Wk  [64:128)=Wq  [128:192)=We  [192:256)=Ww  [256:320)=Wv
__device__ __align__(16) __nv_bfloat16 g_Whi[320 * 512];
__device__ __align__(16) __nv_bfloat16 g_Wlo[320 * 512];

__device__ __forceinline__ float sigmoidf_(float x) {
    return 1.0f / (1.0f + __expf(-x));
}
__device__ __forceinline__ u32 pk(__nv_bfloat16 a, __nv_bfloat16 b) {
    __nv_bfloat162 t = __halves2bfloat162(a, b);   // .x = a = low 16 bits
    return *(u32*)&t;
}
__device__ __forceinline__ void cpasync16(void* s, const void* g) {
    u32 sa = (u32)__cvta_generic_to_shared(s);
    asm volatile("cp.async.cg.shared.global [%0], [%1], 16;\n" :: "r"(sa), "l"(g));
}
__device__ __forceinline__ void mma16816(float* d, const u32* a, const u32* b) {
    asm volatile(
        "mma.sync.aligned.m16n8k16.row.col.f32.bf16.bf16.f32 "
        "{%0,%1,%2,%3},{%4,%5,%6,%7},{%8,%9},{%0,%1,%2,%3};"
        : "+f"(d[0]), "+f"(d[1]), "+f"(d[2]), "+f"(d[3])
        : "r"(a[0]), "r"(a[1]), "r"(a[2]), "r"(a[3]), "r"(b[0]), "r"(b[1]));
}
__device__ __forceinline__ void ldsm_x4(u32* r, u32 saddr) {
    asm volatile("ldmatrix.sync.aligned.m8n8.x4.shared.b16 {%0,%1,%2,%3}, [%4];"
        : "=r"(r[0]), "=r"(r[1]), "=r"(r[2]), "=r"(r[3]) : "r"(saddr));
}
__device__ __forceinline__ void ldsm_x2(u32* r, u32 saddr) {
    asm volatile("ldmatrix.sync.aligned.m8n8.x2.shared.b16 {%0,%1}, [%2];"
        : "=r"(r[0]), "=r"(r[1]) : "r"(saddr));
}

// ---------------------------------------------------------------------------
// W conversion prepass: 5 x [64,512] f32 -> [320,512] bf16 hi/lo.
// ---------------------------------------------------------------------------
__global__ void convw_kernel(const float* __restrict__ Wk, const float* __restrict__ Wq,
                             const float* __restrict__ We, const float* __restrict__ Ww,
                             const float* __restrict__ Wv)
{
    const int row = blockIdx.x;          // 0..319
    const int tid = threadIdx.x;         // 0..127
    const float* src = (row < 64) ? Wk : (row < 128) ? Wq :
                       (row < 192) ? We : (row < 256) ? Ww : Wv;
    const int r = row & 63;
    float4 v = *(const float4*)(src + r * 512 + tid * 4);
    float vv[4] = {v.x, v.y, v.z, v.w};
    __nv_bfloat16 h[4], l[4];
    #pragma unroll
    for (int j = 0; j < 4; j++) {
        h[j] = __float2bfloat16(vv[j]);
        l[j] = __float2bfloat16(vv[j] - __bfloat162float(h[j]));
    }
    *(uint2*)(g_Whi + row * 512 + tid * 4) = make_uint2(pk(h[0], h[1]), pk(h[2], h[3]));
    *(uint2*)(g_Wlo + row * 512 + tid * 4) = make_uint2(pk(l[0], l[1]), pk(l[2], l[3]));
}

// ---------------------------------------------------------------------------
// Gates GEMM on tensor cores (bf16 3-split), ldmatrix fragment loads.
// grid 1024, block 512. CTA: 64 rows x 320 cols, K=512 in 8 chunks of 64.
// (mainloop unchanged from R8; epilogue now writes packed g_kq / g_ewv)
// ---------------------------------------------------------------------------
#define A_ELEMS (64 * 72)
#define B_ELEMS (320 * 72)
#define BBUF_ELEMS (2 * B_ELEMS)
#define SMEM_BYTES ((2 * A_ELEMS + 2 * BBUF_ELEMS) * 2)

__global__ __launch_bounds__(512, 1) void gates_kernel(const float* __restrict__ x)
{
    extern __shared__ char smem_raw[];
    __nv_bfloat16* Ahi = (__nv_bfloat16*)smem_raw;
    __nv_bfloat16* Alo = Ahi + A_ELEMS;
    __nv_bfloat16* Bb  = Alo + A_ELEMS;

    const int tid  = threadIdx.x;
    const int lane = tid & 31;
    const int warp = tid >> 5;
    const int wm = warp >> 3;
    const int wn = warp & 7;
    const int gid = lane >> 2;
    const int t4  = lane & 3;
    const int r0  = blockIdx.x * 64;

    float acc[2][5][4];
    #pragma unroll
    for (int mt = 0; mt < 2; mt++)
        #pragma unroll
        for (int nt = 0; nt < 5; nt++)
            #pragma unroll
            for (int c = 0; c < 4; c++) acc[mt][nt][c] = 0.f;

    const int a_row = tid >> 3;
    const int a_c8  = (tid & 7) * 8;
    const float* a_src = x + (size_t)(r0 + a_row) * 512 + a_c8;

    const u32 inv_a = (u32)(((lane & 15) * 72 + (lane >> 4) * 8) * 2);
    const u32 inv_b = (u32)((((lane >> 4) * 8 + (lane & 7)) * 72 + ((lane >> 3) & 1) * 8) * 2);
    const u32 inv_b2 = (u32)(((lane & 7) * 72 + ((lane >> 3) & 1) * 8) * 2);

    const u32 sAhi = (u32)__cvta_generic_to_shared(Ahi) + (u32)(wm * 32 * 144) + inv_a;
    const u32 sAlo = sAhi + (u32)(A_ELEMS * 2);
    const u32 sB   = (u32)__cvta_generic_to_shared(Bb);
    const u32 bRow = (u32)(wn * 40 * 144);

    #pragma unroll
    for (int it = 0; it < 5; it++) {
        const int idx = tid + it * 512;
        const int row = idx >> 3, seg = idx & 7;
        cpasync16(Bb + row * 72 + seg * 8,            g_Whi + row * 512 + seg * 8);
        cpasync16(Bb + B_ELEMS + row * 72 + seg * 8,  g_Wlo + row * 512 + seg * 8);
    }
    asm volatile("cp.async.commit_group;");
    float4 xa0 = *(const float4*)(a_src);
    float4 xa1 = *(const float4*)(a_src + 4);

    for (int ct = 0; ct < 8; ct++) {
        __syncthreads();
        {
            float vv[8] = {xa0.x, xa0.y, xa0.z, xa0.w, xa1.x, xa1.y, xa1.z, xa1.w};
            __nv_bfloat16 h[8], l[8];
            #pragma unroll
            for (int j = 0; j < 8; j++) {
                h[j] = __float2bfloat16(vv[j]);
                l[j] = __float2bfloat16(vv[j] - __bfloat162float(h[j]));
            }
            *(uint4*)(Ahi + a_row * 72 + a_c8) =
                make_uint4(pk(h[0],h[1]), pk(h[2],h[3]), pk(h[4],h[5]), pk(h[6],h[7]));
            *(uint4*)(Alo + a_row * 72 + a_c8) =
                make_uint4(pk(l[0],l[1]), pk(l[2],l[3]), pk(l[4],l[5]), pk(l[6],l[7]));
        }
        if (ct < 7) {
            const int k0n = (ct + 1) * 64;
            __nv_bfloat16* Bn = Bb + ((ct + 1) & 1) * BBUF_ELEMS;
            #pragma unroll
            for (int it = 0; it < 5; it++) {
                const int idx = tid + it * 512;
                const int row = idx >> 3, seg = idx & 7;
                cpasync16(Bn + row * 72 + seg * 8,           g_Whi + row * 512 + k0n + seg * 8);
                cpasync16(Bn + B_ELEMS + row * 72 + seg * 8, g_Wlo + row * 512 + k0n + seg * 8);
            }
            asm volatile("cp.async.commit_group;");
            xa0 = *(const float4*)(a_src + k0n);
            xa1 = *(const float4*)(a_src + k0n + 4);
            asm volatile("cp.async.wait_group 1;");
        } else {
            asm volatile("cp.async.wait_group 0;");
        }
        __syncthreads();

        const u32 sBhi = sB + (u32)((ct & 1) * BBUF_ELEMS * 2) + bRow;
        const u32 sBlo = sBhi + (u32)(B_ELEMS * 2);

        #pragma unroll
        for (int ks = 0; ks < 4; ks++) {
            const u32 kb = (u32)(ks * 32);
            u32 ah[2][4], al[2][4], bh[5][2], bl[5][2];
            ldsm_x4(ah[0], sAhi + kb);
            ldsm_x4(ah[1], sAhi + 16 * 144 + kb);
            ldsm_x4(al[0], sAlo + kb);
            ldsm_x4(al[1], sAlo + 16 * 144 + kb);
            ldsm_x4(bh[0], sBhi + inv_b + kb);
            ldsm_x4(bh[2], sBhi + 16 * 144 + inv_b + kb);
            ldsm_x2(bh[4], sBhi + 32 * 144 + inv_b2 + kb);
            ldsm_x4(bl[0], sBlo + inv_b + kb);
            ldsm_x4(bl[2], sBlo + 16 * 144 + inv_b + kb);
            ldsm_x2(bl[4], sBlo + 32 * 144 + inv_b2 + kb);

            #pragma unroll
            for (int mt = 0; mt < 2; mt++)
                #pragma unroll
                for (int nt = 0; nt < 5; nt++) mma16816(acc[mt][nt], ah[mt], bh[nt]);
            #pragma unroll
            for (int mt = 0; mt < 2; mt++)
                #pragma unroll
                for (int nt = 0; nt < 5; nt++) mma16816(acc[mt][nt], ah[mt], bl[nt]);
            #pragma unroll
            for (int mt = 0; mt < 2; mt++)
                #pragma unroll
                for (int nt = 0; nt < 5; nt++) mma16816(acc[mt][nt], al[mt], bh[nt]);
        }
    }

    // ---- epilogue: stage D[64][320], fuse activations, write packed arrays ----
    float* Ls = (float*)smem_raw;
    __syncthreads();
    #pragma unroll
    for (int mt = 0; mt < 2; mt++) {
        const int row1 = wm * 32 + mt * 16 + gid;
        #pragma unroll
        for (int nt = 0; nt < 5; nt++) {
            const int col = wn * 40 + nt * 8 + t4 * 2;
            *(float2*)(Ls + row1 * 328 + col)       = make_float2(acc[mt][nt][0], acc[mt][nt][1]);
            *(float2*)(Ls + (row1 + 8) * 328 + col) = make_float2(acc[mt][nt][2], acc[mt][nt][3]);
        }
    }
    __syncthreads();

    if (tid < 256) {
        const int gate = tid >> 7;            // 0=k, 1=q
        const int row  = (tid >> 1) & 63;
        const int part = tid & 1;
        const float* rp = Ls + row * 328 + gate * 64 + part * 32;
        float v[32];
        #pragma unroll
        for (int c = 0; c < 32; c += 4) {
            float4 t4v = *(const float4*)(rp + c);
            v[c] = t4v.x; v[c+1] = t4v.y; v[c+2] = t4v.z; v[c+3] = t4v.w;
        }
        float m = v[0];
        #pragma unroll
        for (int c = 1; c < 32; c++) m = fmaxf(m, v[c]);
        m = fmaxf(m, __shfl_xor_sync(0xffffffffu, m, 1));
        float s = 0.f;
        #pragma unroll
        for (int c = 0; c < 32; c++) { v[c] = __expf(v[c] - m); s += v[c]; }
        s += __shfl_xor_sync(0xffffffffu, s, 1);
        const float inv = 1.0f / s;
        // packed write: g_kq[(row_global*64 + j)*2 + gate]
        float* dst = g_kq + ((size_t)(r0 + row) * 64 + part * 32) * 2 + gate;
        #pragma unroll
        for (int c = 0; c < 32; c++) dst[2 * c] = v[c] * inv;
    } else {
        const int t2 = tid - 256;
        for (int i4 = t2; i4 < 1024; i4 += 256) {
            const int rr = i4 >> 4, c4 = (i4 & 15) * 4;
            float4 a  = *(const float4*)(Ls + rr * 328 + 128 + c4);   // e logits
            float4 w  = *(const float4*)(Ls + rr * 328 + 192 + c4);   // w logits
            float4 vv = *(const float4*)(Ls + rr * 328 + 256 + c4);   // v
            float* base = g_ewv + ((size_t)(r0 + rr) * 64 + c4) * 2;
            *(float4*)(base)     = make_float4(sigmoidf_(a.x), sigmoidf_(w.x) * vv.x,
                                               sigmoidf_(a.y), sigmoidf_(w.y) * vv.y);
            *(float4*)(base + 4) = make_float4(sigmoidf_(a.z), sigmoidf_(w.z) * vv.z,
                                               sigmoidf_(a.w), sigmoidf_(w.w) * vv.w);
        }
    }
}

// ---------------------------------------------------------------------------
// Scan: warp per row (b,i); lane owns cols {2*lane, 2*lane+1}.
// 4096 warps (28/SM), 2 LDG/step (packed kq float4 + ewv float2),
// depth-7 circular register ring, unroll x8.
// ---------------------------------------------------------------------------
__global__ __launch_bounds__(256, 4) void scan_kernel(
    const float* __restrict__ S0,
    float* __restrict__ out,
    float* __restrict__ Sf)
{
    const int b    = blockIdx.y;
    const int warp = threadIdx.x >> 5;
    const int lane = threadIdx.x & 31;
    const int i    = blockIdx.x * 8 + warp;
    const int j0   = lane * 2;

    float2 S = *(const float2*)(S0 + (size_t)b * 4096 + i * 64 + j0);

    const float* kqp  = g_kq  + ((size_t)b * 64 + j0) * 2;
    const float* ewvp = g_ewv + ((size_t)b * 64 + i) * 2;
    float*       op   = out   + b * 64 + i;

    float4 kqb[8];
    float2 eb[8];
    #pragma unroll
    for (int s = 0; s < 7; s++) {                  // prologue t = 0..6
        kqb[s] = *(const float4*)(kqp + s * (BN_ * 2));
        eb[s]  = *(const float2*)(ewvp + s * (BN_ * 2));
    }

    for (int t = 0; t < T_DIM; t += 8) {
        #pragma unroll
        for (int tt = 0; tt < 8; tt++) {
            const int cur = tt;                    // (t+tt)&7 == tt
            const int nxt = (tt + 7) & 7;
            const size_t off = (size_t)(t + tt + 7) * (BN_ * 2);   // padded +8
            kqb[nxt] = *(const float4*)(kqp + off);
            eb[nxt]  = *(const float2*)(ewvp + off);

            const float e = eb[cur].x, wv = eb[cur].y;
            const float4 kq = kqb[cur];            // (k0, q0, k1, q1)

            S.x = fmaf(kq.x, fmaf(-e, S.x, wv), S.x);
            S.y = fmaf(kq.z, fmaf(-e, S.y, wv), S.y);

            float dot = fmaf(S.x, kq.y, S.y * kq.w);
            dot += __shfl_xor_sync(0xffffffffu, dot, 16);
            dot += __shfl_xor_sync(0xffffffffu, dot, 8);
            dot += __shfl_xor_sync(0xffffffffu, dot, 4);
            dot += __shfl_xor_sync(0xffffffffu, dot, 2);
            dot += __shfl_xor_sync(0xffffffffu, dot, 1);

            float xc = fminf(fmaxf(dot, -9.0f), 9.0f);
            float ex = __expf(2.0f * xc);
            float o  = __fdividef(ex - 1.0f, ex + 1.0f);
            if (lane == 0) op[(size_t)(t + tt) * BN_] = o;
        }
    }

    *(float2*)(Sf + (size_t)b * 4096 + i * 64 + j0) = S;
}

// ---------------------------------------------------------------------------
extern "C" void kernel_launch(void* const* d_in, const int* in_sizes, int n_in,
                              void* d_out, int out_size)
{
    const float* x  = (const float*)d_in[0];
    const float* S0 = (const float*)d_in[1];
    const float* Wk = (const float*)d_in[2];
    const float* Wv = (const float*)d_in[3];
    const float* Wq = (const float*)d_in[4];
    const float* We = (const float*)d_in[5];
    const float* Ww = (const float*)d_in[6];

    float* out = (float*)d_out;            // [T,B,N]
    float* Sf  = out + TBN_;               // [B,N,N]

    cudaFuncSetAttribute(gates_kernel,
                         cudaFuncAttributeMaxDynamicSharedMemorySize, SMEM_BYTES);

    convw_kernel<<<320, 128>>>(Wk, Wq, We, Ww, Wv);
    gates_kernel<<<1024, 512, SMEM_BYTES>>>(x);
    scan_kernel<<<dim3(8, B_DIM), 256>>>(S0, out, Sf);
}

// round 10
// speedup vs baseline: 1.1267x; 1.1267x over previous
#include <cuda_runtime.h>
#include <cuda_bf16.h>
#include <math.h>

typedef unsigned int u32;

#define T_DIM 1024
#define B_DIM 64
#define D_DIM 512
#define N_DIM 64
#define BN_ (B_DIM * N_DIM)          /* 4096 */
#define TBN_ (T_DIM * BN_)           /* 4,194,304 */
#define CHUNK_T 256
#define N_CHUNKS 4

// Scratch, padded by EIGHT timesteps for the scan's depth-7 circular prefetch
__device__ float g_k [TBN_ + 8 * BN_];
__device__ float g_q [TBN_ + 8 * BN_];
__device__ float g_e [TBN_ + 8 * BN_];
__device__ float g_wv[TBN_ + 8 * BN_];

// Inter-chunk scan state [b][i][j]
__device__ float g_S[B_DIM * N_DIM * N_DIM];

// Concatenated weights, bf16 hi/lo split. Row order:
// [0:64)=Wk  [64:128)=Wq  [128:192)=We  [192:256)=Ww  [256:320)=Wv
__device__ __align__(16) __nv_bfloat16 g_Whi[320 * 512];
__device__ __align__(16) __nv_bfloat16 g_Wlo[320 * 512];

__device__ __forceinline__ float sigmoidf_(float x) {
    return 1.0f / (1.0f + __expf(-x));
}
__device__ __forceinline__ u32 pk(__nv_bfloat16 a, __nv_bfloat16 b) {
    __nv_bfloat162 t = __halves2bfloat162(a, b);   // .x = a = low 16 bits
    return *(u32*)&t;
}
__device__ __forceinline__ void cpasync16(void* s, const void* g) {
    u32 sa = (u32)__cvta_generic_to_shared(s);
    asm volatile("cp.async.cg.shared.global [%0], [%1], 16;\n" :: "r"(sa), "l"(g));
}
__device__ __forceinline__ void mma16816(float* d, const u32* a, const u32* b) {
    asm volatile(
        "mma.sync.aligned.m16n8k16.row.col.f32.bf16.bf16.f32 "
        "{%0,%1,%2,%3},{%4,%5,%6,%7},{%8,%9},{%0,%1,%2,%3};"
        : "+f"(d[0]), "+f"(d[1]), "+f"(d[2]), "+f"(d[3])
        : "r"(a[0]), "r"(a[1]), "r"(a[2]), "r"(a[3]), "r"(b[0]), "r"(b[1]));
}
__device__ __forceinline__ void ldsm_x4(u32* r, u32 saddr) {
    asm volatile("ldmatrix.sync.aligned.m8n8.x4.shared.b16 {%0,%1,%2,%3}, [%4];"
        : "=r"(r[0]), "=r"(r[1]), "=r"(r[2]), "=r"(r[3]) : "r"(saddr));
}
__device__ __forceinline__ void ldsm_x2(u32* r, u32 saddr) {
    asm volatile("ldmatrix.sync.aligned.m8n8.x2.shared.b16 {%0,%1}, [%2];"
        : "=r"(r[0]), "=r"(r[1]) : "r"(saddr));
}

// ---------------------------------------------------------------------------
// W conversion prepass: 5 x [64,512] f32 -> [320,512] bf16 hi/lo.
// ---------------------------------------------------------------------------
__global__ void convw_kernel(const float* __restrict__ Wk, const float* __restrict__ Wq,
                             const float* __restrict__ We, const float* __restrict__ Ww,
                             const float* __restrict__ Wv)
{
    const int row = blockIdx.x;          // 0..319
    const int tid = threadIdx.x;         // 0..127
    const float* src = (row < 64) ? Wk : (row < 128) ? Wq :
                       (row < 192) ? We : (row < 256) ? Ww : Wv;
    const int r = row & 63;
    float4 v = *(const float4*)(src + r * 512 + tid * 4);
    float vv[4] = {v.x, v.y, v.z, v.w};
    __nv_bfloat16 h[4], l[4];
    #pragma unroll
    for (int j = 0; j < 4; j++) {
        h[j] = __float2bfloat16(vv[j]);
        l[j] = __float2bfloat16(vv[j] - __bfloat162float(h[j]));
    }
    *(uint2*)(g_Whi + row * 512 + tid * 4) = make_uint2(pk(h[0], h[1]), pk(h[2], h[3]));
    *(uint2*)(g_Wlo + row * 512 + tid * 4) = make_uint2(pk(l[0], l[1]), pk(l[2], l[3]));
}

// ---------------------------------------------------------------------------
// Gates GEMM on tensor cores (bf16 3-split), ldmatrix fragment loads.
// Per-chunk: grid 256, block 512. CTA: 64 rows x 320 cols, K=512 in 8 chunks.
// ---------------------------------------------------------------------------
#define A_ELEMS (64 * 72)
#define B_ELEMS (320 * 72)
#define BBUF_ELEMS (2 * B_ELEMS)
#define SMEM_BYTES ((2 * A_ELEMS + 2 * BBUF_ELEMS) * 2)

__global__ __launch_bounds__(512, 1) void gates_kernel(const float* __restrict__ x,
                                                       int r_base)
{
    extern __shared__ char smem_raw[];
    __nv_bfloat16* Ahi = (__nv_bfloat16*)smem_raw;
    __nv_bfloat16* Alo = Ahi + A_ELEMS;
    __nv_bfloat16* Bb  = Alo + A_ELEMS;

    const int tid  = threadIdx.x;
    const int lane = tid & 31;
    const int warp = tid >> 5;
    const int wm = warp >> 3;
    const int wn = warp & 7;
    const int gid = lane >> 2;
    const int t4  = lane & 3;
    const int r0  = r_base + blockIdx.x * 64;

    float acc[2][5][4];
    #pragma unroll
    for (int mt = 0; mt < 2; mt++)
        #pragma unroll
        for (int nt = 0; nt < 5; nt++)
            #pragma unroll
            for (int c = 0; c < 4; c++) acc[mt][nt][c] = 0.f;

    const int a_row = tid >> 3;
    const int a_c8  = (tid & 7) * 8;
    const float* a_src = x + (size_t)(r0 + a_row) * 512 + a_c8;

    const u32 inv_a = (u32)(((lane & 15) * 72 + (lane >> 4) * 8) * 2);
    const u32 inv_b = (u32)((((lane >> 4) * 8 + (lane & 7)) * 72 + ((lane >> 3) & 1) * 8) * 2);
    const u32 inv_b2 = (u32)(((lane & 7) * 72 + ((lane >> 3) & 1) * 8) * 2);

    const u32 sAhi = (u32)__cvta_generic_to_shared(Ahi) + (u32)(wm * 32 * 144) + inv_a;
    const u32 sAlo = sAhi + (u32)(A_ELEMS * 2);
    const u32 sB   = (u32)__cvta_generic_to_shared(Bb);
    const u32 bRow = (u32)(wn * 40 * 144);

    #pragma unroll
    for (int it = 0; it < 5; it++) {
        const int idx = tid + it * 512;
        const int row = idx >> 3, seg = idx & 7;
        cpasync16(Bb + row * 72 + seg * 8,            g_Whi + row * 512 + seg * 8);
        cpasync16(Bb + B_ELEMS + row * 72 + seg * 8,  g_Wlo + row * 512 + seg * 8);
    }
    asm volatile("cp.async.commit_group;");
    float4 xa0 = *(const float4*)(a_src);
    float4 xa1 = *(const float4*)(a_src + 4);

    for (int ct = 0; ct < 8; ct++) {
        __syncthreads();
        {
            float vv[8] = {xa0.x, xa0.y, xa0.z, xa0.w, xa1.x, xa1.y, xa1.z, xa1.w};
            __nv_bfloat16 h[8], l[8];
            #pragma unroll
            for (int j = 0; j < 8; j++) {
                h[j] = __float2bfloat16(vv[j]);
                l[j] = __float2bfloat16(vv[j] - __bfloat162float(h[j]));
            }
            *(uint4*)(Ahi + a_row * 72 + a_c8) =
                make_uint4(pk(h[0],h[1]), pk(h[2],h[3]), pk(h[4],h[5]), pk(h[6],h[7]));
            *(uint4*)(Alo + a_row * 72 + a_c8) =
                make_uint4(pk(l[0],l[1]), pk(l[2],l[3]), pk(l[4],l[5]), pk(l[6],l[7]));
        }
        if (ct < 7) {
            const int k0n = (ct + 1) * 64;
            __nv_bfloat16* Bn = Bb + ((ct + 1) & 1) * BBUF_ELEMS;
            #pragma unroll
            for (int it = 0; it < 5; it++) {
                const int idx = tid + it * 512;
                const int row = idx >> 3, seg = idx & 7;
                cpasync16(Bn + row * 72 + seg * 8,           g_Whi + row * 512 + k0n + seg * 8);
                cpasync16(Bn + B_ELEMS + row * 72 + seg * 8, g_Wlo + row * 512 + k0n + seg * 8);
            }
            asm volatile("cp.async.commit_group;");
            xa0 = *(const float4*)(a_src + k0n);
            xa1 = *(const float4*)(a_src + k0n + 4);
            asm volatile("cp.async.wait_group 1;");
        } else {
            asm volatile("cp.async.wait_group 0;");
        }
        __syncthreads();

        const u32 sBhi = sB + (u32)((ct & 1) * BBUF_ELEMS * 2) + bRow;
        const u32 sBlo = sBhi + (u32)(B_ELEMS * 2);

        #pragma unroll
        for (int ks = 0; ks < 4; ks++) {
            const u32 kb = (u32)(ks * 32);
            u32 ah[2][4], al[2][4], bh[5][2], bl[5][2];
            ldsm_x4(ah[0], sAhi + kb);
            ldsm_x4(ah[1], sAhi + 16 * 144 + kb);
            ldsm_x4(al[0], sAlo + kb);
            ldsm_x4(al[1], sAlo + 16 * 144 + kb);
            ldsm_x4(bh[0], sBhi + inv_b + kb);
            ldsm_x4(bh[2], sBhi + 16 * 144 + inv_b + kb);
            ldsm_x2(bh[4], sBhi + 32 * 144 + inv_b2 + kb);
            ldsm_x4(bl[0], sBlo + inv_b + kb);
            ldsm_x4(bl[2], sBlo + 16 * 144 + inv_b + kb);
            ldsm_x2(bl[4], sBlo + 32 * 144 + inv_b2 + kb);

            #pragma unroll
            for (int mt = 0; mt < 2; mt++)
                #pragma unroll
                for (int nt = 0; nt < 5; nt++) mma16816(acc[mt][nt], ah[mt], bh[nt]);
            #pragma unroll
            for (int mt = 0; mt < 2; mt++)
                #pragma unroll
                for (int nt = 0; nt < 5; nt++) mma16816(acc[mt][nt], ah[mt], bl[nt]);
            #pragma unroll
            for (int mt = 0; mt < 2; mt++)
                #pragma unroll
                for (int nt = 0; nt < 5; nt++) mma16816(acc[mt][nt], al[mt], bh[nt]);
        }
    }

    // ---- epilogue: stage D[64][320] to smem (stride 328), fuse activations ----
    float* Ls = (float*)smem_raw;
    __syncthreads();
    #pragma unroll
    for (int mt = 0; mt < 2; mt++) {
        const int row1 = wm * 32 + mt * 16 + gid;
        #pragma unroll
        for (int nt = 0; nt < 5; nt++) {
            const int col = wn * 40 + nt * 8 + t4 * 2;
            *(float2*)(Ls + row1 * 328 + col)       = make_float2(acc[mt][nt][0], acc[mt][nt][1]);
            *(float2*)(Ls + (row1 + 8) * 328 + col) = make_float2(acc[mt][nt][2], acc[mt][nt][3]);
        }
    }
    __syncthreads();

    if (tid < 256) {
        const int gate = tid >> 7;            // 0=k, 1=q
        const int row  = (tid >> 1) & 63;
        const int part = tid & 1;
        const float* rp = Ls + row * 328 + gate * 64 + part * 32;
        float v[32];
        #pragma unroll
        for (int c = 0; c < 32; c += 4) {
            float4 t4v = *(const float4*)(rp + c);
            v[c] = t4v.x; v[c+1] = t4v.y; v[c+2] = t4v.z; v[c+3] = t4v.w;
        }
        float m = v[0];
        #pragma unroll
        for (int c = 1; c < 32; c++) m = fmaxf(m, v[c]);
        m = fmaxf(m, __shfl_xor_sync(0xffffffffu, m, 1));
        float s = 0.f;
        #pragma unroll
        for (int c = 0; c < 32; c++) { v[c] = __expf(v[c] - m); s += v[c]; }
        s += __shfl_xor_sync(0xffffffffu, s, 1);
        const float inv = 1.0f / s;
        float* dst = ((gate == 0) ? g_k : g_q) + (size_t)(r0 + row) * 64 + part * 32;
        #pragma unroll
        for (int c = 0; c < 32; c += 4)
            *(float4*)(dst + c) = make_float4(v[c]*inv, v[c+1]*inv, v[c+2]*inv, v[c+3]*inv);
    } else {
        const int t2 = tid - 256;
        for (int i4 = t2; i4 < 1024; i4 += 256) {
            const int rr = i4 >> 4, c4 = (i4 & 15) * 4;
            float4 a = *(const float4*)(Ls + rr * 328 + 128 + c4);
            *(float4*)(g_e + (size_t)(r0 + rr) * 64 + c4) =
                make_float4(sigmoidf_(a.x), sigmoidf_(a.y), sigmoidf_(a.z), sigmoidf_(a.w));
        }
        for (int i4 = t2; i4 < 1024; i4 += 256) {
            const int rr = i4 >> 4, c4 = (i4 & 15) * 4;
            float4 w = *(const float4*)(Ls + rr * 328 + 192 + c4);
            float4 vv = *(const float4*)(Ls + rr * 328 + 256 + c4);
            *(float4*)(g_wv + (size_t)(r0 + rr) * 64 + c4) =
                make_float4(sigmoidf_(w.x)*vv.x, sigmoidf_(w.y)*vv.y,
                            sigmoidf_(w.z)*vv.z, sigmoidf_(w.w)*vv.w);
        }
    }
}

// ---------------------------------------------------------------------------
// Scan chunk: 2 rows per warp, depth-7 circular register prefetch, 256 steps.
// First chunk reads S0; last writes Sf; otherwise state lives in g_S.
// ---------------------------------------------------------------------------
__global__ __launch_bounds__(128) void scan_kernel(
    const float* __restrict__ S0,
    float* __restrict__ out,
    float* __restrict__ Sf,
    int t0, int first, int last)
{
    const int b    = blockIdx.y;
    const int warp = threadIdx.x >> 5;
    const int lane = threadIdx.x & 31;
    const int half = lane >> 4;
    const int sub  = lane & 15;
    const int i    = blockIdx.x * 8 + warp * 2 + half;
    const int j0   = sub * 4;

    const float* Sin = first ? S0 : g_S;
    float4 S = *(const float4*)(Sin + (size_t)b * 4096 + i * 64 + j0);

    const float* kp  = g_k  + b * 64 + j0;
    const float* qp  = g_q  + b * 64 + j0;
    const float* ep  = g_e  + b * 64 + i;
    const float* wvp = g_wv + b * 64 + i;
    float*       op  = out  + b * 64 + i;

    float4 kb[8], qb[8];
    float  eb[8], wb[8];
    #pragma unroll
    for (int s = 0; s < 7; s++) {               // prologue: t0 .. t0+6
        const size_t o = (size_t)(t0 + s) * BN_;
        kb[s] = *(const float4*)(kp + o);
        qb[s] = *(const float4*)(qp + o);
        eb[s] = ep[o];
        wb[s] = wvp[o];
    }

    for (int t = t0; t < t0 + CHUNK_T; t += 8) {
        #pragma unroll
        for (int tt = 0; tt < 8; tt++) {
            const int cur = tt;                  // (t+tt)&7 == tt since t%8==0
            const int nxt = (tt + 7) & 7;
            const size_t off = (size_t)(t + tt + 7) * BN_;  // padded +8, safe
            kb[nxt] = *(const float4*)(kp + off);
            qb[nxt] = *(const float4*)(qp + off);
            eb[nxt] = ep[off];
            wb[nxt] = wvp[off];

            const float e = eb[cur], wv = wb[cur];
            const float4 k = kb[cur], q = qb[cur];

            S.x = fmaf(k.x, fmaf(-e, S.x, wv), S.x);
            S.y = fmaf(k.y, fmaf(-e, S.y, wv), S.y);
            S.z = fmaf(k.z, fmaf(-e, S.z, wv), S.z);
            S.w = fmaf(k.w, fmaf(-e, S.w, wv), S.w);

            float dot = fmaf(S.x, q.x, S.y * q.y);
            dot = fmaf(S.z, q.z, dot);
            dot = fmaf(S.w, q.w, dot);
            dot += __shfl_xor_sync(0xffffffffu, dot, 8);
            dot += __shfl_xor_sync(0xffffffffu, dot, 4);
            dot += __shfl_xor_sync(0xffffffffu, dot, 2);
            dot += __shfl_xor_sync(0xffffffffu, dot, 1);

            float xc = fminf(fmaxf(dot, -9.0f), 9.0f);
            float ex = __expf(2.0f * xc);
            float o  = __fdividef(ex - 1.0f, ex + 1.0f);
            if (sub == 0) op[(size_t)(t + tt) * BN_] = o;
        }
    }

    float* Sout = last ? Sf : g_S;
    *(float4*)(Sout + (size_t)b * 4096 + i * 64 + j0) = S;
}

// ---------------------------------------------------------------------------
extern "C" void kernel_launch(void* const* d_in, const int* in_sizes, int n_in,
                              void* d_out, int out_size)
{
    const float* x  = (const float*)d_in[0];
    const float* S0 = (const float*)d_in[1];
    const float* Wk = (const float*)d_in[2];
    const float* Wv = (const float*)d_in[3];
    const float* Wq = (const float*)d_in[4];
    const float* We = (const float*)d_in[5];
    const float* Ww = (const float*)d_in[6];

    float* out = (float*)d_out;            // [T,B,N]
    float* Sf  = out + TBN_;               // [B,N,N]

    static cudaStream_t sB = 0;
    static cudaEvent_t evG[N_CHUNKS];
    static cudaEvent_t evJ = 0;
    static int init_done = 0;
    if (!init_done) {
        cudaFuncSetAttribute(gates_kernel,
                             cudaFuncAttributeMaxDynamicSharedMemorySize, SMEM_BYTES);
        cudaStreamCreateWithFlags(&sB, cudaStreamNonBlocking);
        for (int c = 0; c < N_CHUNKS; c++)
            cudaEventCreateWithFlags(&evG[c], cudaEventDisableTiming);
        cudaEventCreateWithFlags(&evJ, cudaEventDisableTiming);
        init_done = 1;
    }

    convw_kernel<<<320, 128>>>(Wk, Wq, We, Ww, Wv);

    for (int c = 0; c < N_CHUNKS; c++) {
        // gates for timesteps [c*256, (c+1)*256) -> rows [c*16384, ...)
        gates_kernel<<<256, 512, SMEM_BYTES>>>(x, c * (CHUNK_T * B_DIM));
        cudaEventRecord(evG[c], 0);
        cudaStreamWaitEvent(sB, evG[c], 0);
        scan_kernel<<<dim3(8, B_DIM), 128, 0, sB>>>(
            S0, out, Sf, c * CHUNK_T, c == 0, c == N_CHUNKS - 1);
    }
    cudaEventRecord(evJ, sB);
    cudaStreamWaitEvent(0, evJ, 0);
}

// round 11
// speedup vs baseline: 1.3494x; 1.1976x over previous
#include <cuda_runtime.h>
#include <cuda_bf16.h>
#include <math.h>

typedef unsigned int u32;

#define T_DIM 1024
#define B_DIM 64
#define D_DIM 512
#define N_DIM 64
#define BN_ (B_DIM * N_DIM)          /* 4096 */
#define TBN_ (T_DIM * BN_)           /* 4,194,304 */

// Scratch, padded by EIGHT timesteps for the scan's depth-7 circular prefetch
__device__ float g_k [TBN_ + 8 * BN_];
__device__ float g_q [TBN_ + 8 * BN_];
__device__ float g_e [TBN_ + 8 * BN_];
__device__ float g_wv[TBN_ + 8 * BN_];

// Concatenated weights, bf16 hi/lo split. Row order:
// [0:64)=Wk  [64:128)=Wq  [128:192)=We  [192:256)=Ww  [256:320)=Wv
__device__ __align__(16) __nv_bfloat16 g_Whi[320 * 512];
__device__ __align__(16) __nv_bfloat16 g_Wlo[320 * 512];

__device__ __forceinline__ float sigmoidf_(float x) {
    return 1.0f / (1.0f + __expf(-x));
}
__device__ __forceinline__ u32 pk(__nv_bfloat16 a, __nv_bfloat16 b) {
    __nv_bfloat162 t = __halves2bfloat162(a, b);   // .x = a = low 16 bits
    return *(u32*)&t;
}
__device__ __forceinline__ void cpasync16(void* s, const void* g) {
    u32 sa = (u32)__cvta_generic_to_shared(s);
    asm volatile("cp.async.cg.shared.global [%0], [%1], 16;\n" :: "r"(sa), "l"(g));
}
__device__ __forceinline__ void mma16816(float* d, const u32* a, const u32* b) {
    asm volatile(
        "mma.sync.aligned.m16n8k16.row.col.f32.bf16.bf16.f32 "
        "{%0,%1,%2,%3},{%4,%5,%6,%7},{%8,%9},{%0,%1,%2,%3};"
        : "+f"(d[0]), "+f"(d[1]), "+f"(d[2]), "+f"(d[3])
        : "r"(a[0]), "r"(a[1]), "r"(a[2]), "r"(a[3]), "r"(b[0]), "r"(b[1]));
}
__device__ __forceinline__ void ldsm_x4(u32* r, u32 saddr) {
    asm volatile("ldmatrix.sync.aligned.m8n8.x4.shared.b16 {%0,%1,%2,%3}, [%4];"
        : "=r"(r[0]), "=r"(r[1]), "=r"(r[2]), "=r"(r[3]) : "r"(saddr));
}
__device__ __forceinline__ void ldsm_x2(u32* r, u32 saddr) {
    asm volatile("ldmatrix.sync.aligned.m8n8.x2.shared.b16 {%0,%1}, [%2];"
        : "=r"(r[0]), "=r"(r[1]) : "r"(saddr));
}

// ---------------------------------------------------------------------------
// W conversion prepass: 5 x [64,512] f32 -> [320,512] bf16 hi/lo.
// ---------------------------------------------------------------------------
__global__ void convw_kernel(const float* __restrict__ Wk, const float* __restrict__ Wq,
                             const float* __restrict__ We, const float* __restrict__ Ww,
                             const float* __restrict__ Wv)
{
    const int row = blockIdx.x;          // 0..319
    const int tid = threadIdx.x;         // 0..127
    const float* src = (row < 64) ? Wk : (row < 128) ? Wq :
                       (row < 192) ? We : (row < 256) ? Ww : Wv;
    const int r = row & 63;
    float4 v = *(const float4*)(src + r * 512 + tid * 4);
    float vv[4] = {v.x, v.y, v.z, v.w};
    __nv_bfloat16 h[4], l[4];
    #pragma unroll
    for (int j = 0; j < 4; j++) {
        h[j] = __float2bfloat16(vv[j]);
        l[j] = __float2bfloat16(vv[j] - __bfloat162float(h[j]));
    }
    *(uint2*)(g_Whi + row * 512 + tid * 4) = make_uint2(pk(h[0], h[1]), pk(h[2], h[3]));
    *(uint2*)(g_Wlo + row * 512 + tid * 4) = make_uint2(pk(l[0], l[1]), pk(l[2], l[3]));
}

// ---------------------------------------------------------------------------
// Gates GEMM on tensor cores (bf16 3-split), ldmatrix fragment loads.
// grid 1024, block 512. CTA: 64 rows x 320 cols, K=512 in 8 chunks of 64.
// (unchanged from R8 — at the mma.sync-path ceiling)
// ---------------------------------------------------------------------------
#define A_ELEMS (64 * 72)
#define B_ELEMS (320 * 72)
#define BBUF_ELEMS (2 * B_ELEMS)
#define SMEM_BYTES ((2 * A_ELEMS + 2 * BBUF_ELEMS) * 2)

__global__ __launch_bounds__(512, 1) void gates_kernel(const float* __restrict__ x)
{
    extern __shared__ char smem_raw[];
    __nv_bfloat16* Ahi = (__nv_bfloat16*)smem_raw;
    __nv_bfloat16* Alo = Ahi + A_ELEMS;
    __nv_bfloat16* Bb  = Alo + A_ELEMS;

    const int tid  = threadIdx.x;
    const int lane = tid & 31;
    const int warp = tid >> 5;
    const int wm = warp >> 3;
    const int wn = warp & 7;
    const int gid = lane >> 2;
    const int t4  = lane & 3;
    const int r0  = blockIdx.x * 64;

    float acc[2][5][4];
    #pragma unroll
    for (int mt = 0; mt < 2; mt++)
        #pragma unroll
        for (int nt = 0; nt < 5; nt++)
            #pragma unroll
            for (int c = 0; c < 4; c++) acc[mt][nt][c] = 0.f;

    const int a_row = tid >> 3;
    const int a_c8  = (tid & 7) * 8;
    const float* a_src = x + (size_t)(r0 + a_row) * 512 + a_c8;

    const u32 inv_a = (u32)(((lane & 15) * 72 + (lane >> 4) * 8) * 2);
    const u32 inv_b = (u32)((((lane >> 4) * 8 + (lane & 7)) * 72 + ((lane >> 3) & 1) * 8) * 2);
    const u32 inv_b2 = (u32)(((lane & 7) * 72 + ((lane >> 3) & 1) * 8) * 2);

    const u32 sAhi = (u32)__cvta_generic_to_shared(Ahi) + (u32)(wm * 32 * 144) + inv_a;
    const u32 sAlo = sAhi + (u32)(A_ELEMS * 2);
    const u32 sB   = (u32)__cvta_generic_to_shared(Bb);
    const u32 bRow = (u32)(wn * 40 * 144);

    #pragma unroll
    for (int it = 0; it < 5; it++) {
        const int idx = tid + it * 512;
        const int row = idx >> 3, seg = idx & 7;
        cpasync16(Bb + row * 72 + seg * 8,            g_Whi + row * 512 + seg * 8);
        cpasync16(Bb + B_ELEMS + row * 72 + seg * 8,  g_Wlo + row * 512 + seg * 8);
    }
    asm volatile("cp.async.commit_group;");
    float4 xa0 = *(const float4*)(a_src);
    float4 xa1 = *(const float4*)(a_src + 4);

    for (int ct = 0; ct < 8; ct++) {
        __syncthreads();
        {
            float vv[8] = {xa0.x, xa0.y, xa0.z, xa0.w, xa1.x, xa1.y, xa1.z, xa1.w};
            __nv_bfloat16 h[8], l[8];
            #pragma unroll
            for (int j = 0; j < 8; j++) {
                h[j] = __float2bfloat16(vv[j]);
                l[j] = __float2bfloat16(vv[j] - __bfloat162float(h[j]));
            }
            *(uint4*)(Ahi + a_row * 72 + a_c8) =
                make_uint4(pk(h[0],h[1]), pk(h[2],h[3]), pk(h[4],h[5]), pk(h[6],h[7]));
            *(uint4*)(Alo + a_row * 72 + a_c8) =
                make_uint4(pk(l[0],l[1]), pk(l[2],l[3]), pk(l[4],l[5]), pk(l[6],l[7]));
        }
        if (ct < 7) {
            const int k0n = (ct + 1) * 64;
            __nv_bfloat16* Bn = Bb + ((ct + 1) & 1) * BBUF_ELEMS;
            #pragma unroll
            for (int it = 0; it < 5; it++) {
                const int idx = tid + it * 512;
                const int row = idx >> 3, seg = idx & 7;
                cpasync16(Bn + row * 72 + seg * 8,           g_Whi + row * 512 + k0n + seg * 8);
                cpasync16(Bn + B_ELEMS + row * 72 + seg * 8, g_Wlo + row * 512 + k0n + seg * 8);
            }
            asm volatile("cp.async.commit_group;");
            xa0 = *(const float4*)(a_src + k0n);
            xa1 = *(const float4*)(a_src + k0n + 4);
            asm volatile("cp.async.wait_group 1;");
        } else {
            asm volatile("cp.async.wait_group 0;");
        }
        __syncthreads();

        const u32 sBhi = sB + (u32)((ct & 1) * BBUF_ELEMS * 2) + bRow;
        const u32 sBlo = sBhi + (u32)(B_ELEMS * 2);

        #pragma unroll
        for (int ks = 0; ks < 4; ks++) {
            const u32 kb = (u32)(ks * 32);
            u32 ah[2][4], al[2][4], bh[5][2], bl[5][2];
            ldsm_x4(ah[0], sAhi + kb);
            ldsm_x4(ah[1], sAhi + 16 * 144 + kb);
            ldsm_x4(al[0], sAlo + kb);
            ldsm_x4(al[1], sAlo + 16 * 144 + kb);
            ldsm_x4(bh[0], sBhi + inv_b + kb);
            ldsm_x4(bh[2], sBhi + 16 * 144 + inv_b + kb);
            ldsm_x2(bh[4], sBhi + 32 * 144 + inv_b2 + kb);
            ldsm_x4(bl[0], sBlo + inv_b + kb);
            ldsm_x4(bl[2], sBlo + 16 * 144 + inv_b + kb);
            ldsm_x2(bl[4], sBlo + 32 * 144 + inv_b2 + kb);

            #pragma unroll
            for (int mt = 0; mt < 2; mt++)
                #pragma unroll
                for (int nt = 0; nt < 5; nt++) mma16816(acc[mt][nt], ah[mt], bh[nt]);
            #pragma unroll
            for (int mt = 0; mt < 2; mt++)
                #pragma unroll
                for (int nt = 0; nt < 5; nt++) mma16816(acc[mt][nt], ah[mt], bl[nt]);
            #pragma unroll
            for (int mt = 0; mt < 2; mt++)
                #pragma unroll
                for (int nt = 0; nt < 5; nt++) mma16816(acc[mt][nt], al[mt], bh[nt]);
        }
    }

    // ---- epilogue: stage D[64][320] to smem (stride 328), fuse activations ----
    float* Ls = (float*)smem_raw;
    __syncthreads();
    #pragma unroll
    for (int mt = 0; mt < 2; mt++) {
        const int row1 = wm * 32 + mt * 16 + gid;
        #pragma unroll
        for (int nt = 0; nt < 5; nt++) {
            const int col = wn * 40 + nt * 8 + t4 * 2;
            *(float2*)(Ls + row1 * 328 + col)       = make_float2(acc[mt][nt][0], acc[mt][nt][1]);
            *(float2*)(Ls + (row1 + 8) * 328 + col) = make_float2(acc[mt][nt][2], acc[mt][nt][3]);
        }
    }
    __syncthreads();

    if (tid < 256) {
        const int gate = tid >> 7;            // 0=k, 1=q
        const int row  = (tid >> 1) & 63;
        const int part = tid & 1;
        const float* rp = Ls + row * 328 + gate * 64 + part * 32;
        float v[32];
        #pragma unroll
        for (int c = 0; c < 32; c += 4) {
            float4 t4v = *(const float4*)(rp + c);
            v[c] = t4v.x; v[c+1] = t4v.y; v[c+2] = t4v.z; v[c+3] = t4v.w;
        }
        float m = v[0];
        #pragma unroll
        for (int c = 1; c < 32; c++) m = fmaxf(m, v[c]);
        m = fmaxf(m, __shfl_xor_sync(0xffffffffu, m, 1));
        float s = 0.f;
        #pragma unroll
        for (int c = 0; c < 32; c++) { v[c] = __expf(v[c] - m); s += v[c]; }
        s += __shfl_xor_sync(0xffffffffu, s, 1);
        const float inv = 1.0f / s;
        float* dst = ((gate == 0) ? g_k : g_q) + (size_t)(r0 + row) * 64 + part * 32;
        #pragma unroll
        for (int c = 0; c < 32; c += 4)
            *(float4*)(dst + c) = make_float4(v[c]*inv, v[c+1]*inv, v[c+2]*inv, v[c+3]*inv);
    } else {
        const int t2 = tid - 256;
        for (int i4 = t2; i4 < 1024; i4 += 256) {
            const int rr = i4 >> 4, c4 = (i4 & 15) * 4;
            float4 a = *(const float4*)(Ls + rr * 328 + 128 + c4);
            *(float4*)(g_e + (size_t)(r0 + rr) * 64 + c4) =
                make_float4(sigmoidf_(a.x), sigmoidf_(a.y), sigmoidf_(a.z), sigmoidf_(a.w));
        }
        for (int i4 = t2; i4 < 1024; i4 += 256) {
            const int rr = i4 >> 4, c4 = (i4 & 15) * 4;
            float4 w = *(const float4*)(Ls + rr * 328 + 192 + c4);
            float4 vv = *(const float4*)(Ls + rr * 328 + 256 + c4);
            *(float4*)(g_wv + (size_t)(r0 + rr) * 64 + c4) =
                make_float4(sigmoidf_(w.x)*vv.x, sigmoidf_(w.y)*vv.y,
                            sigmoidf_(w.z)*vv.z, sigmoidf_(w.w)*vv.w);
        }
    }
}

// ---------------------------------------------------------------------------
// Scan: 2 rows per warp, depth-7 circular prefetch, unroll x8 — with BATCHED
// reduction tails: 8 S-updates bank 8 per-lane partial dots, then the 8
// independent 4-shfl butterflies + tanhs + stores issue together so their
// latencies overlap instead of serializing per step.
// ---------------------------------------------------------------------------
__global__ __launch_bounds__(128) void scan_kernel(
    const float* __restrict__ S0,
    float* __restrict__ out,
    float* __restrict__ Sf)
{
    const int b    = blockIdx.y;
    const int warp = threadIdx.x >> 5;
    const int lane = threadIdx.x & 31;
    const int half = lane >> 4;
    const int sub  = lane & 15;
    const int i    = blockIdx.x * 8 + warp * 2 + half;
    const int j0   = sub * 4;

    float4 S = *(const float4*)(S0 + (size_t)b * 4096 + i * 64 + j0);

    const float* kp  = g_k  + b * 64 + j0;
    const float* qp  = g_q  + b * 64 + j0;
    const float* ep  = g_e  + b * 64 + i;
    const float* wvp = g_wv + b * 64 + i;
    float*       op  = out  + b * 64 + i;

    float4 kb[8], qb[8];
    float  eb[8], wb[8];
    #pragma unroll
    for (int s = 0; s < 7; s++) {               // prologue: t = 0..6
        kb[s] = *(const float4*)(kp + s * BN_);
        qb[s] = *(const float4*)(qp + s * BN_);
        eb[s] = ep[s * BN_];
        wb[s] = wvp[s * BN_];
    }

    for (int t = 0; t < T_DIM; t += 8) {
        float dots[8];
        // phase 1: 8 S-updates + per-lane partial dots (no cross-lane ops)
        #pragma unroll
        for (int tt = 0; tt < 8; tt++) {
            const int cur = tt;                  // (t+tt)&7 == tt since t%8==0
            const int nxt = (tt + 7) & 7;
            const int off = (t + tt + 7) * BN_;  // padded +8, safe at end
            kb[nxt] = *(const float4*)(kp + off);
            qb[nxt] = *(const float4*)(qp + off);
            eb[nxt] = ep[off];
            wb[nxt] = wvp[off];

            const float e = eb[cur], wv = wb[cur];
            const float4 k = kb[cur], q = qb[cur];

            S.x = fmaf(k.x, fmaf(-e, S.x, wv), S.x);
            S.y = fmaf(k.y, fmaf(-e, S.y, wv), S.y);
            S.z = fmaf(k.z, fmaf(-e, S.z, wv), S.z);
            S.w = fmaf(k.w, fmaf(-e, S.w, wv), S.w);

            float d = fmaf(S.x, q.x, S.y * q.y);
            d = fmaf(S.z, q.z, d);
            dots[tt] = fmaf(S.w, q.w, d);
        }
        // phase 2: 8 independent butterfly reductions (latencies overlap)
        #pragma unroll
        for (int tt = 0; tt < 8; tt++)
            dots[tt] += __shfl_xor_sync(0xffffffffu, dots[tt], 8);
        #pragma unroll
        for (int tt = 0; tt < 8; tt++)
            dots[tt] += __shfl_xor_sync(0xffffffffu, dots[tt], 4);
        #pragma unroll
        for (int tt = 0; tt < 8; tt++)
            dots[tt] += __shfl_xor_sync(0xffffffffu, dots[tt], 2);
        #pragma unroll
        for (int tt = 0; tt < 8; tt++)
            dots[tt] += __shfl_xor_sync(0xffffffffu, dots[tt], 1);
        // phase 3: 8 pipelined tanhs + stores
        #pragma unroll
        for (int tt = 0; tt < 8; tt++) {
            float xc = fminf(fmaxf(dots[tt], -9.0f), 9.0f);
            float ex = __expf(2.0f * xc);
            float o  = __fdividef(ex - 1.0f, ex + 1.0f);
            if (sub == 0) op[(size_t)(t + tt) * BN_] = o;
        }
    }

    *(float4*)(Sf + (size_t)b * 4096 + i * 64 + j0) = S;
}

// ---------------------------------------------------------------------------
extern "C" void kernel_launch(void* const* d_in, const int* in_sizes, int n_in,
                              void* d_out, int out_size)
{
    const float* x  = (const float*)d_in[0];
    const float* S0 = (const float*)d_in[1];
    const float* Wk = (const float*)d_in[2];
    const float* Wv = (const float*)d_in[3];
    const float* Wq = (const float*)d_in[4];
    const float* We = (const float*)d_in[5];
    const float* Ww = (const float*)d_in[6];

    float* out = (float*)d_out;            // [T,B,N]
    float* Sf  = out + TBN_;               // [B,N,N]

    cudaFuncSetAttribute(gates_kernel,
                         cudaFuncAttributeMaxDynamicSharedMemorySize, SMEM_BYTES);

    convw_kernel<<<320, 128>>>(Wk, Wq, We, Ww, Wv);
    gates_kernel<<<1024, 512, SMEM_BYTES>>>(x);
    scan_kernel<<<dim3(8, B_DIM), 128>>>(S0, out, Sf);
}